// round 17
// baseline (speedup 1.0000x reference)
#include <cuda_runtime.h>
#include <math.h>
#include <stdint.h>

// Problem constants (fixed shapes per reference)
#define N_NODES 100000
#define N_EDGES 1600000
#define F_IN    256
#define F_OUT   128
#define ALPHA   0.2f

typedef unsigned long long ull;

// ---------------- device scratch (static; no allocation allowed) ----------------
__device__ __align__(16) float g_h[(size_t)N_NODES * F_OUT];   // 51.2 MB: h = x @ W
__device__ float g_sl[N_NODES];
__device__ float g_sr[N_NODES];
__device__ int   g_deg[N_NODES];
__device__ int   g_off[N_NODES + 1];
__device__ int   g_cur[N_NODES];
__device__ int   g_src[N_EDGES];
__device__ int   g_is64;

// ---------------- warp reduction helpers ----------------
__device__ __forceinline__ float warpSum(float v) {
#pragma unroll
    for (int o = 16; o > 0; o >>= 1) v += __shfl_xor_sync(0xffffffffu, v, o);
    return v;
}

// packed dual-fp32 FMA (PTX 8.6, sm_100+): acc = a*b + acc, lanewise on 2 floats
#define FMA2(acc, a, b) \
    asm volatile("fma.rn.f32x2 %0, %1, %2, %0;" : "+l"(acc) : "l"(a), "l"(b))

// ---------------- 0) edge dtype detection ----------------
// int64 little-endian with values < 2^31 has zero hi-words at odd int32 slots.
__global__ void detect_kernel(const int* __restrict__ p) {
    int lane = threadIdx.x;
    int bad = 0;
    for (int k = lane; k < 256; k += 32)
        if (p[2 * k + 1] != 0) bad = 1;
    unsigned b = __ballot_sync(0xffffffffu, bad);
    if (lane == 0) g_is64 = (b == 0) ? 1 : 0;
}
__device__ __forceinline__ int edge_at(const void* eidx, long long elem) {
    if (g_is64) return (int)((const long long*)eidx)[elem];
    return ((const int*)eidx)[elem];
}

// ---------------- 1) f32x2 register-blocked GEMM: h = x @ W (+ fused scores) ----------
// CTA tile 128x128, 16x16 threads, 8x8 outputs/thread. A staged TRANSPOSED and
// PRE-DUPLICATED as (a,a) float2 -> per k: 6 LDS.128 + 32 FMA2, zero dup-MOVs.
#define KC      32
#define APITCH2 130            // float2 units; row = 1040B (16B-aligned, bank-spread)
#define A_BYTES (KC * APITCH2 * 8)          // 33280
#define B_BYTES (KC * 128 * 4)              // 16384
#define SM_GEMM (A_BYTES + B_BYTES)         // 49664 -> dynamic smem
__global__ __launch_bounds__(256) void gemm_kernel(
    const float* __restrict__ x, const float* __restrict__ w,
    const float* __restrict__ a_l, const float* __restrict__ a_r, int n)
{
    extern __shared__ __align__(16) char smem[];
    float2 (*As2)[APITCH2] = (float2(*)[APITCH2])smem;        // [k][row] dup pairs
    float  (*Bs)[128]      = (float(*)[128])(smem + A_BYTES); // [k][col]

    const int tid = threadIdx.x;
    const int tx  = tid & 15;
    const int ty  = tid >> 4;
    const int rowBase = blockIdx.x * 128;

    ull acc2[8][4];
#pragma unroll
    for (int i = 0; i < 8; i++)
#pragma unroll
        for (int j = 0; j < 4; j++) acc2[i][j] = 0ull;

    for (int k0 = 0; k0 < F_IN; k0 += KC) {
        // stage A transposed + duplicated: 128 rows x KC = 1024 float4 reads, 4/thread
#pragma unroll
        for (int l = 0; l < 4; l++) {
            int idx = tid + l * 256;       // 0..1023
            int r   = idx >> 3;            // row 0..127
            int q   = idx & 7;             // k-quad 0..7
            float4 v = make_float4(0.f, 0.f, 0.f, 0.f);
            int gr = rowBase + r;
            if (gr < n)
                v = *(const float4*)(x + (size_t)gr * F_IN + k0 + q * 4);
            As2[q * 4 + 0][r] = make_float2(v.x, v.x);
            As2[q * 4 + 1][r] = make_float2(v.y, v.y);
            As2[q * 4 + 2][r] = make_float2(v.z, v.z);
            As2[q * 4 + 3][r] = make_float2(v.w, v.w);
        }
        // stage B: KC x 128 = 1024 float4 reads, 4/thread
#pragma unroll
        for (int l = 0; l < 4; l++) {
            int idx = tid + l * 256;
            int r   = idx >> 5;            // k row 0..31
            int c4  = idx & 31;            // col quad
            *(float4*)&Bs[r][c4 * 4] =
                *(const float4*)(w + (size_t)(k0 + r) * F_OUT + c4 * 4);
        }
        __syncthreads();

#pragma unroll 8
        for (int k = 0; k < KC; k++) {
            // A: 8 dup-pairs via 4 LDS.128 (2 distinct addrs per phase -> ~free)
            ull a[8];
            *(uint4*)&a[0] = *(const uint4*)&As2[k][ty * 4];
            *(uint4*)&a[2] = *(const uint4*)&As2[k][ty * 4 + 2];
            *(uint4*)&a[4] = *(const uint4*)&As2[k][64 + ty * 4];
            *(uint4*)&a[6] = *(const uint4*)&As2[k][64 + ty * 4 + 2];
            // B: 8 col values via 2 LDS.128, used directly as 4 f32x2 pairs
            ull b[4];
            *(uint4*)&b[0] = *(const uint4*)&Bs[k][tx * 4];
            *(uint4*)&b[2] = *(const uint4*)&Bs[k][64 + tx * 4];
#pragma unroll
            for (int i = 0; i < 8; i++)
#pragma unroll
                for (int j = 0; j < 4; j++)
                    FMA2(acc2[i][j], a[i], b[j]);
        }
        __syncthreads();
    }

    // ---- epilogue: store h + fused scores (dot a_l/a_r, reduce over 16 tx lanes) ----
    float alv[8], arv[8];
#pragma unroll
    for (int jj = 0; jj < 4; jj++) {
        alv[jj]     = __ldg(a_l + tx * 4 + jj);
        alv[4 + jj] = __ldg(a_l + 64 + tx * 4 + jj);
        arv[jj]     = __ldg(a_r + tx * 4 + jj);
        arv[4 + jj] = __ldg(a_r + 64 + tx * 4 + jj);
    }
#pragma unroll
    for (int i = 0; i < 8; i++) {
        const int lr = (i < 4) ? (ty * 4 + i) : (64 + ty * 4 + (i - 4));
        const int gr = rowBase + lr;
        float2 c0 = *(float2*)&acc2[i][0];
        float2 c1 = *(float2*)&acc2[i][1];
        float2 c2 = *(float2*)&acc2[i][2];
        float2 c3 = *(float2*)&acc2[i][3];
        float pl = c0.x * alv[0] + c0.y * alv[1] + c1.x * alv[2] + c1.y * alv[3]
                 + c2.x * alv[4] + c2.y * alv[5] + c3.x * alv[6] + c3.y * alv[7];
        float pr = c0.x * arv[0] + c0.y * arv[1] + c1.x * arv[2] + c1.y * arv[3]
                 + c2.x * arv[4] + c2.y * arv[5] + c3.x * arv[6] + c3.y * arv[7];
#pragma unroll
        for (int o = 1; o < 16; o <<= 1) {          // reduce across the 16 tx lanes
            pl += __shfl_xor_sync(0xffffffffu, pl, o);
            pr += __shfl_xor_sync(0xffffffffu, pr, o);
        }
        if (gr < n) {
            *(float4*)(g_h + (size_t)gr * F_OUT + tx * 4) =
                make_float4(c0.x, c0.y, c1.x, c1.y);
            *(float4*)(g_h + (size_t)gr * F_OUT + 64 + tx * 4) =
                make_float4(c2.x, c2.y, c3.x, c3.y);
            if (tx == 0) { g_sl[gr] = pl; g_sr[gr] = pr; }
        }
    }
}

// ---------------- 2) CSR build ----------------
__global__ void zero_deg_kernel(int n) {
    int i = blockIdx.x * blockDim.x + threadIdx.x;
    if (i < n) g_deg[i] = 0;
}
__global__ void hist_kernel(const void* __restrict__ eidx, int e) {
    int i = blockIdx.x * blockDim.x + threadIdx.x;
    if (i < e) atomicAdd(&g_deg[edge_at(eidx, i)], 1);
}
__global__ __launch_bounds__(1024) void scan_kernel(int n) {
    __shared__ int sh_warp[32];
    __shared__ int sh_total;
    const int tid  = threadIdx.x;
    const int lane = tid & 31;
    const int wid  = tid >> 5;
    int running = 0;
    for (int base = 0; base < n; base += 1024) {
        int i = base + tid;
        int v = (i < n) ? g_deg[i] : 0;
        int incl = v;
#pragma unroll
        for (int o = 1; o < 32; o <<= 1) {
            int t = __shfl_up_sync(0xffffffffu, incl, o);
            if (lane >= o) incl += t;
        }
        if (lane == 31) sh_warp[wid] = incl;
        __syncthreads();
        if (tid < 32) {
            int ws = sh_warp[tid];
            int wi = ws;
#pragma unroll
            for (int o = 1; o < 32; o <<= 1) {
                int t = __shfl_up_sync(0xffffffffu, wi, o);
                if (tid >= o) wi += t;
            }
            sh_warp[tid] = wi - ws;   // exclusive warp offset
        }
        __syncthreads();
        int excl = incl - v + sh_warp[wid];
        if (i < n) { g_off[i] = running + excl; g_cur[i] = running + excl; }
        if (tid == 1023) sh_total = excl + v;
        __syncthreads();
        running += sh_total;
        __syncthreads();
    }
    if (tid == 0) g_off[n] = running;
}
__global__ void fill_kernel(const void* __restrict__ eidx, int e) {
    int i = blockIdx.x * blockDim.x + threadIdx.x;
    if (i < e) {
        int r = edge_at(eidx, i);
        int c = edge_at(eidx, (long long)e + i);
        int p = atomicAdd(&g_cur[r], 1);
        g_src[p] = c;
    }
}

// ---------------- 3) fused softmax + SpMM + bias + gated encoder ----------------
// One warp per destination node. Pass 1: online (max,sum) with NaN-safe merge.
// Pass 2: serial-j broadcast loop — every lane loads c/g_sr (warp-uniform addr ->
// 1-sector broadcast), computes w redundantly, gathers its own 16B of h[c]. No shfls.
__global__ __launch_bounds__(256) void aggregate_kernel(
    const float* __restrict__ bias, const float* __restrict__ fc,
    const float* __restrict__ bf, float* __restrict__ out, int n)
{
    const int node = (blockIdx.x * blockDim.x + threadIdx.x) >> 5;
    const int lane = threadIdx.x & 31;
    if (node >= n) return;

    const int s = g_off[node];
    const int e = g_off[node + 1];
    const float sl = g_sl[node];

    // pass 1: online per-lane (max, sum-of-exp)
    float m = -INFINITY, sum = 0.f;
    for (int j = s + lane; j < e; j += 32) {
        int c = g_src[j];
        float v = sl + g_sr[c];
        v = v > 0.f ? v : ALPHA * v;
        if (v > m) { sum = sum * __expf(m - v) + 1.f; m = v; }
        else       { sum += __expf(v - m); }
    }
    // cross-lane merge. NaN-guard: when m == mn (incl. both -inf) weight is exactly 1,
    // avoiding exp(-inf - -inf) = exp(NaN).
#pragma unroll
    for (int o = 16; o > 0; o >>= 1) {
        float m2 = __shfl_xor_sync(0xffffffffu, m, o);
        float s2 = __shfl_xor_sync(0xffffffffu, sum, o);
        float mn = fmaxf(m, m2);
        float w1 = (m  == mn) ? 1.f : __expf(m  - mn);
        float w2 = (m2 == mn) ? 1.f : __expf(m2 - mn);
        sum = sum * w1 + s2 * w2;
        m = mn;
    }
    const float inv = 1.f / (sum + 1e-16f);

    // pass 2: weighted accumulation of h[src] rows (lane owns 4 features)
    float4 acc = make_float4(0.f, 0.f, 0.f, 0.f);
    const float* hlane = g_h + lane * 4;
#pragma unroll 4
    for (int j = s; j < e; j++) {
        int c = __ldg(&g_src[j]);                 // warp-uniform -> broadcast
        float v = sl + __ldg(&g_sr[c]);           // warp-uniform -> broadcast
        v = v > 0.f ? v : ALPHA * v;
        float w = __expf(v - m) * inv;
        const float4 hv = *(const float4*)(hlane + (size_t)c * F_OUT);
        acc.x += w * hv.x;
        acc.y += w * hv.y;
        acc.z += w * hv.z;
        acc.w += w * hv.w;
    }

    // epilogue: + bias, sigmoid gate, relu(v) + gate*min(v,0)
    float4 bsv = *(const float4*)(bias + lane * 4);
    float4 v = make_float4(acc.x + bsv.x, acc.y + bsv.y, acc.z + bsv.z, acc.w + bsv.w);
    float4 fv = *(const float4*)(fc + lane * 4);
    float p = v.x * fv.x + v.y * fv.y + v.z * fv.z + v.w * fv.w;
    p = warpSum(p) + bf[0];
    float gate = 1.f / (1.f + __expf(-p));

    float4 o;
    o.x = (v.x < 0.f ? 0.f : v.x) + gate * (v.x > 0.f ? 0.f : v.x);
    o.y = (v.y < 0.f ? 0.f : v.y) + gate * (v.y > 0.f ? 0.f : v.y);
    o.z = (v.z < 0.f ? 0.f : v.z) + gate * (v.z > 0.f ? 0.f : v.z);
    o.w = (v.w < 0.f ? 0.f : v.w) + gate * (v.w > 0.f ? 0.f : v.w);
    *(float4*)(out + (size_t)node * F_OUT + lane * 4) = o;
}

// ---------------- launch ----------------
// NOTE: gemm_kernel stays the 4th launch — that's the one ncu's window captures.
extern "C" void kernel_launch(void* const* d_in, const int* in_sizes, int n_in,
                              void* d_out, int out_size)
{
    const float* x      = (const float*)d_in[0];
    const void*  eidx   = d_in[1];               // [2, E]; int32 or int64 (detected)
    // d_in[2] = edge_attr (unused by the reference)
    const float* weight = (const float*)d_in[3];
    const float* bias   = (const float*)d_in[4];
    const float* a_l    = (const float*)d_in[5];
    const float* a_r    = (const float*)d_in[6];
    const float* fc     = (const float*)d_in[7];
    const float* bf     = (const float*)d_in[8];
    float*       out    = (float*)d_out;

    const int n = in_sizes[0] / F_IN;    // 100000
    const int e = in_sizes[1] / 2;       // 1600000

    cudaFuncSetAttribute(gemm_kernel,
                         cudaFuncAttributeMaxDynamicSharedMemorySize, SM_GEMM);

    detect_kernel<<<1, 32>>>((const int*)eidx);                   // 1
    zero_deg_kernel<<<(n + 255) / 256, 256>>>(n);                 // 2
    hist_kernel<<<(e + 255) / 256, 256>>>(eidx, e);               // 3
    gemm_kernel<<<(n + 127) / 128, 256, SM_GEMM>>>(x, weight, a_l, a_r, n); // 4 <- profiled
    scan_kernel<<<1, 1024>>>(n);                                  // 5
    fill_kernel<<<(e + 255) / 256, 256>>>(eidx, e);               // 6
    aggregate_kernel<<<(n + 7) / 8, 256>>>(bias, fc, bf, out, n); // 7
}